// round 8
// baseline (speedup 1.0000x reference)
#include <cuda_runtime.h>

// Shapes: field/gt_field (8,4,64,128,64) f32, ct/gt_ct (8,1) f32, sdf (8,1,64,128,64) f32.
// Output: scalar f32 total loss. Single fused kernel, float4 along W,
// shfl x-edges, batched y/z neighbor loads (16 LDG.128 in flight), 3 CTAs/SM.

#define NB 8
#define ND 64
#define NH 128
#define NW 64
#define SP (ND*NH*NW)
#define CS SP
#define NPTS (NB*SP)
#define NVEC (NPTS/4)          // 1048576 float4 quads
#define NBLK (NVEC/256)        // 4096 blocks

#define DXd ((2.0 + 0.5) / 63.0)
#define DYd ((0.5 + 0.5) / 127.0)
#define DZd ((0.3 + 0.5) / 63.0)

constexpr float c_inv2dx = (float)(1.0 / (2.0 * DXd));
constexpr float c_inv2dy = (float)(1.0 / (2.0 * DYd));
constexpr float c_inv2dz = (float)(1.0 / (2.0 * DZd));
constexpr float c_idx2   = (float)(1.0 / (DXd * DXd));
constexpr float c_idy2   = (float)(1.0 / (DYd * DYd));
constexpr float c_idz2   = (float)(1.0 / (DZd * DZd));
constexpr float c_idyz2  = (float)(1.0 / (DYd * DYd) + 1.0 / (DZd * DZd));

constexpr float c_sc_field  = (float)(1.0  / (double)(NB*4*SP));
constexpr float c_sc_ct     = (float)(10.0 / 8.0);
constexpr float c_sc_cm     = (float)(1.0  / (double)(NB*(ND-2)*(NH-2)*(NW-2)));
constexpr float c_sc_noslip = (float)(10.0 / (double)NPTS);
constexpr float c_sc_inlet  = (float)(5.0  / (double)(NB*ND*NH));
constexpr float c_sc_outlet = (float)(1.0  / (double)(NB*ND*NH));

#define INV_RE 1.0e-6f
#define OY NW
#define OZ (NH*NW)
#define FULLMASK 0xffffffffu

__device__ double g_acc = 0.0;
__device__ unsigned int g_count = 0;

__device__ __forceinline__ float4 ld4(const float* p) {
    return *reinterpret_cast<const float4*>(p);
}
__device__ __forceinline__ float4 ld4cs(const float* p) {
    return __ldcs(reinterpret_cast<const float4*>(p));
}
__device__ __forceinline__ void f4arr(float4 t, float* a) {
    a[0] = t.x; a[1] = t.y; a[2] = t.z; a[3] = t.w;
}

__global__ void __launch_bounds__(256, 3) k_loss(
    const float* __restrict__ field,
    const float* __restrict__ ct,
    const float* __restrict__ gt_field,
    const float* __restrict__ gt_ct,
    const float* __restrict__ sdf,
    float* __restrict__ out)
{
    const int vid = blockIdx.x * 256 + threadIdx.x;   // exactly NVEC threads
    const int wq = vid & 15;
    const int h  = (vid >> 4)  & (NH - 1);
    const int d  = (vid >> 11) & (ND - 1);
    const int b  = vid >> 17;

    const int sidx  = ((d * NH + h) << 6) + (wq << 2);
    const float* fb = field    + b * (4 * SP) + sidx;
    const float* gb = gt_field + b * (4 * SP) + sidx;

    const bool yz_interior = (d >= 1) & (d <= ND - 2) & (h >= 1) & (h <= NH - 2);

    float acc = 0.0f;

    if (vid < 8) {
        float dct = ct[vid] - gt_ct[vid];
        acc += c_sc_ct * dct * dct;
    }

    // centers, all 4 channels (u,v,w,p)
    float Fc[4][4];
    #pragma unroll
    for (int c = 0; c < 4; c++) f4arr(ld4(fb + c * CS), Fc[c]);

    // ---- batched neighbor loads: all 16 LDG.128 issued back-to-back ----
    float4 ypv[4], ymv[4], zpv[4], zmv[4];
    if (yz_interior) {
        #pragma unroll
        for (int c = 0; c < 4; c++) {
            ypv[c] = ld4(fb + c * CS + OY);
            ymv[c] = ld4(fb + c * CS - OY);
            zpv[c] = ld4(fb + c * CS + OZ);
            zmv[c] = ld4(fb + c * CS - OZ);
        }
    }

    // ---- independent work overlaps the neighbor-load latency ----

    // field MSE (gt streamed)
    {
        float m = 0.0f;
        #pragma unroll
        for (int c = 0; c < 4; c++) {
            float4 g = ld4cs(gb + c * CS);
            float d0 = Fc[c][0] - g.x, d1 = Fc[c][1] - g.y;
            float d2 = Fc[c][2] - g.z, d3 = Fc[c][3] - g.w;
            m += d0*d0 + d1*d1 + d2*d2 + d3*d3;
        }
        acc += c_sc_field * m;
    }

    float4 svv = ld4cs(sdf + b * SP + sidx);
    float Sv[4]; f4arr(svv, Sv);

    // no-slip (sdf <= 0)
    {
        float m = 0.0f;
        #pragma unroll
        for (int l = 0; l < 4; l++) {
            float q = Fc[0][l]*Fc[0][l] + Fc[1][l]*Fc[1][l] + Fc[2][l]*Fc[2][l];
            m += (Sv[l] <= 0.0f) ? q : 0.0f;
        }
        acc += c_sc_noslip * m;
    }

    // inlet / outlet
    if (wq == 0) {
        float du0 = Fc[0][0] - 1.0f;
        acc += c_sc_inlet * (du0*du0 + Fc[1][0]*Fc[1][0] + Fc[2][0]*Fc[2][0]);
    }
    if (wq == 15) {
        float a0 = Fc[0][3] - Fc[0][2];
        float a1 = Fc[1][3] - Fc[1][2];
        float a2 = Fc[2][3] - Fc[2][2];
        acc += c_sc_outlet * (a0*a0 + a1*a1 + a2*a2);
    }

    // x-edge neighbors via warp shuffle (uniform, full warp; garbage lanes
    // are zero-masked by wgt[] below)
    float Lcs[4], Rcs[4];
    #pragma unroll
    for (int c = 0; c < 4; c++) {
        Lcs[c] = __shfl_up_sync  (FULLMASK, Fc[c][3], 1);
        Rcs[c] = __shfl_down_sync(FULLMASK, Fc[c][0], 1);
    }

    // ---- interior continuity + momentum ----
    if (yz_interior) {
        // reduce the 16 staged vectors into compact arrays
        float gy[4][4], gz[4][4], lyz[3][4];
        #pragma unroll
        for (int c = 0; c < 4; c++) {
            float yp[4], ym[4], zp[4], zm[4];
            f4arr(ypv[c], yp); f4arr(ymv[c], ym);
            f4arr(zpv[c], zp); f4arr(zmv[c], zm);
            #pragma unroll
            for (int l = 0; l < 4; l++) {
                gy[c][l] = (yp[l] - ym[l]) * c_inv2dy;
                gz[c][l] = (zp[l] - zm[l]) * c_inv2dz;
            }
            if (c < 3) {
                #pragma unroll
                for (int l = 0; l < 4; l++)
                    lyz[c][l] = (yp[l] + ym[l]) * c_idy2
                              + (zp[l] + zm[l]) * c_idz2;
            }
        }

        float wgt[4];
        wgt[0] = (wq != 0  && Sv[0] > 0.0f) ? 1.0f : 0.0f;
        wgt[1] = (Sv[1] > 0.0f) ? 1.0f : 0.0f;
        wgt[2] = (Sv[2] > 0.0f) ? 1.0f : 0.0f;
        wgt[3] = (wq != 15 && Sv[3] > 0.0f) ? 1.0f : 0.0f;

        float msum = 0.0f;
        #pragma unroll
        for (int l = 0; l < 4; l++) {
            float xm[4], xp[4];
            #pragma unroll
            for (int c = 0; c < 4; c++) {
                xm[c] = (l == 0) ? Lcs[c] : Fc[c][l - 1];
                xp[c] = (l == 3) ? Rcs[c] : Fc[c][l + 1];
            }
            const float u = Fc[0][l], v = Fc[1][l], wv = Fc[2][l];

            float gxu = (xp[0] - xm[0]) * c_inv2dx;
            float gxv = (xp[1] - xm[1]) * c_inv2dx;
            float gxw = (xp[2] - xm[2]) * c_inv2dx;
            float gxp = (xp[3] - xm[3]) * c_inv2dx;

            float div = gxu + gy[1][l] + gz[2][l];

            float lap_u = (xp[0] + xm[0] - 2.0f*u ) * c_idx2 + lyz[0][l] - 2.0f*u  * c_idyz2;
            float lap_v = (xp[1] + xm[1] - 2.0f*v ) * c_idx2 + lyz[1][l] - 2.0f*v  * c_idyz2;
            float lap_w = (xp[2] + xm[2] - 2.0f*wv) * c_idx2 + lyz[2][l] - 2.0f*wv * c_idyz2;

            float rx = u*gxu + v*gy[0][l] + wv*gz[0][l] + gxp      - INV_RE*lap_u;
            float ry = u*gxv + v*gy[1][l] + wv*gz[1][l] + gy[3][l] - INV_RE*lap_v;
            float rz = u*gxw + v*gy[2][l] + wv*gz[2][l] + gz[3][l] - INV_RE*lap_w;

            msum += wgt[l] * (div*div + rx*rx + ry*ry + rz*rz);
        }
        acc += c_sc_cm * msum;
    }

    // ---- reduction: warp shfl (f32) -> block (f64) -> global atomic ----
    #pragma unroll
    for (int o = 16; o > 0; o >>= 1)
        acc += __shfl_down_sync(FULLMASK, acc, o);

    __shared__ double warpsum[8];
    if ((threadIdx.x & 31) == 0)
        warpsum[threadIdx.x >> 5] = (double)acc;
    __syncthreads();

    if (threadIdx.x == 0) {
        double t = 0.0;
        #pragma unroll
        for (int i = 0; i < 8; i++) t += warpsum[i];
        atomicAdd(&g_acc, t);
        __threadfence();
        unsigned int ticket = atomicAdd(&g_count, 1u);
        if (ticket == (unsigned)(gridDim.x - 1)) {
            double tot = atomicAdd(&g_acc, 0.0);
            out[0] = (float)tot;
            g_acc = 0.0;       // reset for next graph replay
            g_count = 0u;
            __threadfence();
        }
    }
}

extern "C" void kernel_launch(void* const* d_in, const int* in_sizes, int n_in,
                              void* d_out, int out_size)
{
    const float* field    = (const float*)d_in[0];
    const float* ct       = (const float*)d_in[1];
    const float* gt_field = (const float*)d_in[2];
    const float* gt_ct    = (const float*)d_in[3];
    const float* sdf      = (const float*)d_in[4];

    k_loss<<<NBLK, 256>>>(field, ct, gt_field, gt_ct, sdf, (float*)d_out);
}

// round 9
// speedup vs baseline: 1.5108x; 1.5108x over previous
#include <cuda_runtime.h>

// Shapes: field/gt_field (8,4,64,128,64) f32, ct/gt_ct (8,1) f32, sdf (8,1,64,128,64) f32.
// Output: scalar f32 total loss. Single fused kernel, float4 along W,
// channel-streamed interior, shfl x-edges, batched DRAM front loads.

#define NB 8
#define ND 64
#define NH 128
#define NW 64
#define SP (ND*NH*NW)
#define CS SP
#define NPTS (NB*SP)
#define NVEC (NPTS/4)          // 1048576 float4 quads
#define NBLK (NVEC/256)        // 4096 blocks

#define DXd ((2.0 + 0.5) / 63.0)
#define DYd ((0.5 + 0.5) / 127.0)
#define DZd ((0.3 + 0.5) / 63.0)

constexpr float c_inv2dx = (float)(1.0 / (2.0 * DXd));
constexpr float c_inv2dy = (float)(1.0 / (2.0 * DYd));
constexpr float c_inv2dz = (float)(1.0 / (2.0 * DZd));
constexpr float c_idx2   = (float)(1.0 / (DXd * DXd));
constexpr float c_idy2   = (float)(1.0 / (DYd * DYd));
constexpr float c_idz2   = (float)(1.0 / (DZd * DZd));

constexpr float c_sc_field  = (float)(1.0  / (double)(NB*4*SP));
constexpr float c_sc_ct     = (float)(10.0 / 8.0);
constexpr float c_sc_cm     = (float)(1.0  / (double)(NB*(ND-2)*(NH-2)*(NW-2)));
constexpr float c_sc_noslip = (float)(10.0 / (double)NPTS);
constexpr float c_sc_inlet  = (float)(5.0  / (double)(NB*ND*NH));
constexpr float c_sc_outlet = (float)(1.0  / (double)(NB*ND*NH));

#define INV_RE 1.0e-6f
#define OY NW
#define OZ (NH*NW)
#define FULLMASK 0xffffffffu

__device__ double g_acc = 0.0;
__device__ unsigned int g_count = 0;

__device__ __forceinline__ float4 ld4(const float* p) {
    return *reinterpret_cast<const float4*>(p);
}
__device__ __forceinline__ float4 ld4cs(const float* p) {
    return __ldcs(reinterpret_cast<const float4*>(p));
}

__global__ void __launch_bounds__(256, 4) k_loss(
    const float* __restrict__ field,
    const float* __restrict__ ct,
    const float* __restrict__ gt_field,
    const float* __restrict__ gt_ct,
    const float* __restrict__ sdf,
    float* __restrict__ out)
{
    const int vid = blockIdx.x * 256 + threadIdx.x;   // exactly NVEC threads
    const int wq = vid & 15;
    const int h  = (vid >> 4)  & (NH - 1);
    const int d  = (vid >> 11) & (ND - 1);
    const int b  = vid >> 17;

    const int sidx  = ((d * NH + h) << 6) + (wq << 2);
    const float* fb = field    + b * (4 * SP) + sidx;
    const float* gb = gt_field + b * (4 * SP) + sidx;

    float acc = 0.0f;

    if (vid < 8) {
        float dct = ct[vid] - gt_ct[vid];
        acc += c_sc_ct * dct * dct;
    }

    // ---- batched DRAM front loads: 9 LDG.128 issued back-to-back ----
    float4 cv[4], gv[4], svv;
    #pragma unroll
    for (int c = 0; c < 4; c++) cv[c] = ld4(fb + c * CS);
    #pragma unroll
    for (int c = 0; c < 4; c++) gv[c] = ld4cs(gb + c * CS);
    svv = ld4cs(sdf + b * SP + sidx);

    // velocity centers persist as scalars
    float Fv[3][4];
    #pragma unroll
    for (int c = 0; c < 3; c++) {
        Fv[c][0] = cv[c].x; Fv[c][1] = cv[c].y;
        Fv[c][2] = cv[c].z; Fv[c][3] = cv[c].w;
    }

    // field MSE, all 4 channels
    {
        float m = 0.0f;
        #pragma unroll
        for (int c = 0; c < 4; c++) {
            float d0 = cv[c].x - gv[c].x, d1 = cv[c].y - gv[c].y;
            float d2 = cv[c].z - gv[c].z, d3 = cv[c].w - gv[c].w;
            m += d0*d0 + d1*d1 + d2*d2 + d3*d3;
        }
        acc += c_sc_field * m;
    }

    float Sv[4] = {svv.x, svv.y, svv.z, svv.w};

    // no-slip (sdf <= 0)
    {
        float m = 0.0f;
        #pragma unroll
        for (int l = 0; l < 4; l++) {
            float q = Fv[0][l]*Fv[0][l] + Fv[1][l]*Fv[1][l] + Fv[2][l]*Fv[2][l];
            m += (Sv[l] <= 0.0f) ? q : 0.0f;
        }
        acc += c_sc_noslip * m;
    }

    // inlet / outlet
    if (wq == 0) {
        float du0 = Fv[0][0] - 1.0f;
        acc += c_sc_inlet * (du0*du0 + Fv[1][0]*Fv[1][0] + Fv[2][0]*Fv[2][0]);
    }
    if (wq == 15) {
        float a0 = Fv[0][3] - Fv[0][2];
        float a1 = Fv[1][3] - Fv[1][2];
        float a2 = Fv[2][3] - Fv[2][2];
        acc += c_sc_outlet * (a0*a0 + a1*a1 + a2*a2);
    }

    const bool yz_interior = (d >= 1) & (d <= ND - 2) & (h >= 1) & (h <= NH - 2);

    // ---- x-edge neighbors via warp shuffle (uniform, full warp) ----
    // Row-crossing lanes (wq==0/15) are zero-masked by wgt[] below.
    float Lcs[3], Rcs[3];
    #pragma unroll
    for (int c = 0; c < 3; c++) {
        Lcs[c] = __shfl_up_sync  (FULLMASK, Fv[c][3], 1);
        Rcs[c] = __shfl_down_sync(FULLMASK, Fv[c][0], 1);
    }

    // --- pressure block: gradients; p regs die at end of block ---
    float gpx[4], gpy[4], gpz[4];
    {
        float4 pc = cv[3];
        float pL = __shfl_up_sync  (FULLMASK, pc.w, 1);
        float pR = __shfl_down_sync(FULLMASK, pc.x, 1);
        if (yz_interior) {
            const float* cb = fb + 3 * CS;
            float4 yp = ld4(cb + OY), ym = ld4(cb - OY);
            float4 zp = ld4(cb + OZ), zm = ld4(cb - OZ);
            gpy[0] = (yp.x - ym.x) * c_inv2dy;
            gpy[1] = (yp.y - ym.y) * c_inv2dy;
            gpy[2] = (yp.z - ym.z) * c_inv2dy;
            gpy[3] = (yp.w - ym.w) * c_inv2dy;
            gpz[0] = (zp.x - zm.x) * c_inv2dz;
            gpz[1] = (zp.y - zm.y) * c_inv2dz;
            gpz[2] = (zp.z - zm.z) * c_inv2dz;
            gpz[3] = (zp.w - zm.w) * c_inv2dz;
            gpx[0] = (pc.y - pL)   * c_inv2dx;
            gpx[1] = (pc.z - pc.x) * c_inv2dx;
            gpx[2] = (pc.w - pc.y) * c_inv2dx;
            gpx[3] = (pR   - pc.z) * c_inv2dx;
        }
    }

    // --- interior continuity + momentum, velocity channels streamed ---
    if (yz_interior) {
        float wgt[4];
        wgt[0] = (wq != 0  && Sv[0] > 0.0f) ? 1.0f : 0.0f;
        wgt[1] = (Sv[1] > 0.0f) ? 1.0f : 0.0f;
        wgt[2] = (Sv[2] > 0.0f) ? 1.0f : 0.0f;
        wgt[3] = (wq != 15 && Sv[3] > 0.0f) ? 1.0f : 0.0f;

        float div[4] = {0.0f, 0.0f, 0.0f, 0.0f};
        float msum = 0.0f;

        #pragma unroll
        for (int c = 0; c < 3; c++) {
            const float* cb = fb + c * CS;
            float4 yp = ld4(cb + OY), ym = ld4(cb - OY);
            float4 zp = ld4(cb + OZ), zm = ld4(cb - OZ);

            float gy[4], sy[4], gz[4], sz[4];
            gy[0] = (yp.x - ym.x) * c_inv2dy; sy[0] = yp.x + ym.x;
            gy[1] = (yp.y - ym.y) * c_inv2dy; sy[1] = yp.y + ym.y;
            gy[2] = (yp.z - ym.z) * c_inv2dy; sy[2] = yp.z + ym.z;
            gy[3] = (yp.w - ym.w) * c_inv2dy; sy[3] = yp.w + ym.w;
            gz[0] = (zp.x - zm.x) * c_inv2dz; sz[0] = zp.x + zm.x;
            gz[1] = (zp.y - zm.y) * c_inv2dz; sz[1] = zp.y + zm.y;
            gz[2] = (zp.z - zm.z) * c_inv2dz; sz[2] = zp.z + zm.z;
            gz[3] = (zp.w - zm.w) * c_inv2dz; sz[3] = zp.w + zm.w;

            #pragma unroll
            for (int l = 0; l < 4; l++) {
                float ce = Fv[c][l];
                float xm = (l == 0) ? Lcs[c] : Fv[c][l - 1];
                float xp = (l == 3) ? Rcs[c] : Fv[c][l + 1];
                float gx = (xp - xm) * c_inv2dx;
                float lap = (xp + xm - 2.0f * ce) * c_idx2
                          + (sy[l]   - 2.0f * ce) * c_idy2
                          + (sz[l]   - 2.0f * ce) * c_idz2;
                float gp  = (c == 0) ? gpx[l] : (c == 1) ? gpy[l] : gpz[l];
                float res = Fv[0][l] * gx + Fv[1][l] * gy[l] + Fv[2][l] * gz[l]
                          + gp - INV_RE * lap;
                msum   += wgt[l] * res * res;
                div[l] += (c == 0) ? gx : (c == 1) ? gy[l] : gz[l];
            }
        }

        #pragma unroll
        for (int l = 0; l < 4; l++)
            msum += wgt[l] * div[l] * div[l];

        acc += c_sc_cm * msum;
    }

    // ---- reduction: warp shfl (f32) -> block (f64) -> global atomic ----
    #pragma unroll
    for (int o = 16; o > 0; o >>= 1)
        acc += __shfl_down_sync(FULLMASK, acc, o);

    __shared__ double warpsum[8];
    if ((threadIdx.x & 31) == 0)
        warpsum[threadIdx.x >> 5] = (double)acc;
    __syncthreads();

    if (threadIdx.x == 0) {
        double t = 0.0;
        #pragma unroll
        for (int i = 0; i < 8; i++) t += warpsum[i];
        atomicAdd(&g_acc, t);
        __threadfence();
        unsigned int ticket = atomicAdd(&g_count, 1u);
        if (ticket == (unsigned)(gridDim.x - 1)) {
            double tot = atomicAdd(&g_acc, 0.0);
            out[0] = (float)tot;
            g_acc = 0.0;       // reset for next graph replay
            g_count = 0u;
            __threadfence();
        }
    }
}

extern "C" void kernel_launch(void* const* d_in, const int* in_sizes, int n_in,
                              void* d_out, int out_size)
{
    const float* field    = (const float*)d_in[0];
    const float* ct       = (const float*)d_in[1];
    const float* gt_field = (const float*)d_in[2];
    const float* gt_ct    = (const float*)d_in[3];
    const float* sdf      = (const float*)d_in[4];

    k_loss<<<NBLK, 256>>>(field, ct, gt_field, gt_ct, sdf, (float*)d_out);
}